// round 7
// baseline (speedup 1.0000x reference)
#include <cuda_runtime.h>

#define IN_F 8192
#define OUT_F 8192
#define THRESH_F 50.0f
#define ROWS_PER_BLOCK 8
#define THREADS 256
#define MV_BLOCKS 512                         // single wave (<= 888 resident)
#define ROW_GROUPS 2                          // 512 * 2 * 8 = 8192 rows
#define N_GROUPS (MV_BLOCKS * ROW_GROUPS)     // 1024 partials
#define UPD_BLOCKS 256
#define UPD_THREADS 32

// Scratch between kernels (no allocations allowed). Fully overwritten every
// launch -> deterministic across graph replays.
__device__ float g_current[OUT_F];
__device__ __align__(16) float g_partial[N_GROUPS];   // per-group spike counts

// Kernel 1: binarized matvec + spike decision + per-group spike partial.
// Single-wave grid: 512 blocks x 2 row-groups each, spike vector staged once.
// Inner loop body is the proven R2/R4 body — do not touch.
__global__ void __launch_bounds__(THREADS) snn_matvec_kernel(
    const float* __restrict__ spike_input,   // [IN_F]
    const float* __restrict__ syn,           // [OUT_F, IN_F] row-major
    const float* __restrict__ v_mem,         // [OUT_F]
    const float* __restrict__ v_th,          // [OUT_F]
    const float* __restrict__ noise,         // [OUT_F]
    float* __restrict__ out)                 // out[0:OUT_F] = spikes
{
    __shared__ float4 s_spike[IN_F / 4];     // 32 KB
    __shared__ float  s_spk[ROWS_PER_BLOCK];

    const int tid = threadIdx.x;

    // Stage spike vector into shared (reused by all 16 rows in this block).
    const float4* sp4 = reinterpret_cast<const float4*>(spike_input);
    #pragma unroll
    for (int i = 0; i < (IN_F / 4) / THREADS; i++) {
        s_spike[tid + i * THREADS] = sp4[tid + i * THREADS];
    }
    __syncthreads();

    const int warp = tid >> 5;
    const int lane = tid & 31;

    #pragma unroll
    for (int g = 0; g < ROW_GROUPS; g++) {
        const int group = blockIdx.x + g * MV_BLOCKS;
        const int row   = group * ROWS_PER_BLOCK + warp;

        const float4* r4 = reinterpret_cast<const float4*>(syn + (size_t)row * IN_F);

        float acc0 = 0.0f, acc1 = 0.0f;
        // 2048 float4 per row / 32 lanes = 64 float4 per lane; 2 per iter.
        #pragma unroll 8
        for (int it = 0; it < (IN_F / 8) / 32; it++) {
            const int i0 = (it * 2 + 0) * 32 + lane;
            const int i1 = (it * 2 + 1) * 32 + lane;
            const float4 w0 = r4[i0];
            const float4 w1 = r4[i1];
            const float4 s0 = s_spike[i0];
            const float4 s1 = s_spike[i1];
            if (w0.x > THRESH_F) acc0 += s0.x;
            if (w0.y > THRESH_F) acc1 += s0.y;
            if (w0.z > THRESH_F) acc0 += s0.z;
            if (w0.w > THRESH_F) acc1 += s0.w;
            if (w1.x > THRESH_F) acc0 += s1.x;
            if (w1.y > THRESH_F) acc1 += s1.y;
            if (w1.z > THRESH_F) acc0 += s1.z;
            if (w1.w > THRESH_F) acc1 += s1.w;
        }
        float acc = acc0 + acc1;

        // Warp reduce (exact: small integers).
        #pragma unroll
        for (int o = 16; o > 0; o >>= 1) {
            acc += __shfl_xor_sync(0xFFFFFFFFu, acc, o);
        }

        if (lane == 0) {
            g_current[row] = acc;
            const float pot = v_mem[row] + acc + noise[row];
            const float spk = (pot >= v_th[row]) ? 1.0f : 0.0f;
            out[row] = spk;
            s_spk[warp] = spk;
        }
        __syncthreads();

        if (tid == 0) {
            float p = 0.0f;
            #pragma unroll
            for (int w = 0; w < ROWS_PER_BLOCK; w++) p += s_spk[w];
            g_partial[group] = p;
        }
        if (g + 1 < ROW_GROUPS) __syncthreads();   // s_spk reuse
    }
}

// Kernel 2: PDL-launched. Independent loads before the grid dependency wait,
// dependent reads after. 256 blocks x 32 threads (one warp, no smem).
__global__ void __launch_bounds__(UPD_THREADS) snn_update_kernel(
    const float* __restrict__ v_mem,
    const float* __restrict__ v_th,
    float* __restrict__ out)   // [spikes | v_mem_new | v_th_new]
{
    const int tid = threadIdx.x;   // 0..31
    const int o   = blockIdx.x * UPD_THREADS + tid;

    // Independent of the matvec: issue before the grid dependency wait.
    const float vm  = v_mem[o];
    const float vt0 = v_th[o];

#if __CUDA_ARCH__ >= 900
    cudaGridDependencySynchronize();
#endif

    // Dependent loads.
    const float s   = out[o];
    const float cur = g_current[o];

    // 1024 partials = 256 float4; 8 float4 per lane, coalesced, L2-hot.
    const float4* p4 = reinterpret_cast<const float4*>(g_partial);
    float local = 0.0f;
    #pragma unroll
    for (int i = 0; i < 8; i++) {
        const float4 a = p4[tid + i * 32];
        local += (a.x + a.y) + (a.z + a.w);
    }
    #pragma unroll
    for (int off = 16; off > 0; off >>= 1) {
        local += __shfl_xor_sync(0xFFFFFFFFu, local, off);
    }

    const float inhibition = local * 0.5f;

    const float v_new = (vm - inhibition + cur) * (1.0f - s) * 0.5f;

    float vt = vt0 + (s - 0.1f) * 0.01f;
    vt = fminf(fmaxf(vt, 0.2f), 5.0f);

    out[OUT_F + o]     = v_new;
    out[2 * OUT_F + o] = vt;
}

extern "C" void kernel_launch(void* const* d_in, const int* in_sizes, int n_in,
                              void* d_out, int out_size)
{
    const float* spike_input = (const float*)d_in[0];   // [1, 8192]
    const float* syn         = (const float*)d_in[1];   // [8192, 8192]
    const float* v_mem       = (const float*)d_in[2];   // [8192]
    const float* v_th        = (const float*)d_in[3];   // [8192]
    const float* noise       = (const float*)d_in[4];   // [8192]
    float* out = (float*)d_out;                          // 3 * 8192 floats

    snn_matvec_kernel<<<MV_BLOCKS, THREADS>>>(
        spike_input, syn, v_mem, v_th, noise, out);

    cudaLaunchAttribute attrs[1];
    attrs[0].id = cudaLaunchAttributeProgrammaticStreamSerialization;
    attrs[0].val.programmaticStreamSerializationAllowed = 1;

    cudaLaunchConfig_t cfg = {};
    cfg.gridDim  = dim3(UPD_BLOCKS, 1, 1);
    cfg.blockDim = dim3(UPD_THREADS, 1, 1);
    cfg.dynamicSmemBytes = 0;
    cfg.stream = 0;
    cfg.attrs = attrs;
    cfg.numAttrs = 1;
    cudaLaunchKernelEx(&cfg, snn_update_kernel, v_mem, v_th, (float*)out);
}

// round 8
// speedup vs baseline: 1.0014x; 1.0014x over previous
#include <cuda_runtime.h>

#define IN_F 8192
#define OUT_F 8192
#define THRESH_F 50.0f
#define ROWS_PER_BLOCK 8
#define THREADS 256
#define MV_BLOCKS 512                         // single wave, grid barrier safe
#define ROW_GROUPS 2                          // 512 * 2 * 8 = 8192 rows
#define N_GROUPS (MV_BLOCKS * ROW_GROUPS)     // 1024 partials
#define EPI_ROWS (OUT_F / MV_BLOCKS)          // 16 rows per block epilogue

// Scratch (no allocations allowed). g_done is a MONOTONIC arrival counter:
// never reset, so it is race-free across CUDA-graph replays (each launch
// advances it by exactly MV_BLOCKS; wrap handled with signed distance).
__device__ float g_current[OUT_F];
__device__ __align__(16) float g_partial[N_GROUPS];
__device__ unsigned int g_done = 0;

// Fused kernel: matvec + spike decision, grid-wide spin barrier, then a
// fully distributed state-update epilogue (16 rows per block).
// min-blocks 4 => regs capped at 64 (slack vs natural ~48) => >=592 resident
// blocks guaranteed => 512-block spin barrier cannot deadlock.
__global__ void __launch_bounds__(THREADS, 4) snn_fused_kernel(
    const float* __restrict__ spike_input,   // [IN_F]
    const float* __restrict__ syn,           // [OUT_F, IN_F] row-major
    const float* __restrict__ v_mem,         // [OUT_F]
    const float* __restrict__ v_th,          // [OUT_F]
    const float* __restrict__ noise,         // [OUT_F]
    float* __restrict__ out)                 // [spikes | v_mem_new | v_th_new]
{
    __shared__ float4 s_spike[IN_F / 4];     // 32 KB
    __shared__ float  s_spk[ROWS_PER_BLOCK];
    __shared__ float  s_red[THREADS / 32];

    const int tid = threadIdx.x;

    // Stage spike vector into shared (reused by all 16 rows in this block).
    const float4* sp4 = reinterpret_cast<const float4*>(spike_input);
    #pragma unroll
    for (int i = 0; i < (IN_F / 4) / THREADS; i++) {
        s_spike[tid + i * THREADS] = sp4[tid + i * THREADS];
    }
    __syncthreads();

    const int warp = tid >> 5;
    const int lane = tid & 31;

    #pragma unroll
    for (int g = 0; g < ROW_GROUPS; g++) {
        const int group = blockIdx.x + g * MV_BLOCKS;
        const int row   = group * ROWS_PER_BLOCK + warp;

        const float4* r4 = reinterpret_cast<const float4*>(syn + (size_t)row * IN_F);

        float acc0 = 0.0f, acc1 = 0.0f;
        // Proven R2/R4 body: 64 float4 per lane; 2 per iter, predicated adds.
        #pragma unroll 8
        for (int it = 0; it < (IN_F / 8) / 32; it++) {
            const int i0 = (it * 2 + 0) * 32 + lane;
            const int i1 = (it * 2 + 1) * 32 + lane;
            const float4 w0 = r4[i0];
            const float4 w1 = r4[i1];
            const float4 s0 = s_spike[i0];
            const float4 s1 = s_spike[i1];
            if (w0.x > THRESH_F) acc0 += s0.x;
            if (w0.y > THRESH_F) acc1 += s0.y;
            if (w0.z > THRESH_F) acc0 += s0.z;
            if (w0.w > THRESH_F) acc1 += s0.w;
            if (w1.x > THRESH_F) acc0 += s1.x;
            if (w1.y > THRESH_F) acc1 += s1.y;
            if (w1.z > THRESH_F) acc0 += s1.z;
            if (w1.w > THRESH_F) acc1 += s1.w;
        }
        float acc = acc0 + acc1;

        #pragma unroll
        for (int o = 16; o > 0; o >>= 1) {
            acc += __shfl_xor_sync(0xFFFFFFFFu, acc, o);
        }

        if (lane == 0) {
            g_current[row] = acc;
            const float pot = v_mem[row] + acc + noise[row];
            const float spk = (pot >= v_th[row]) ? 1.0f : 0.0f;
            out[row] = spk;
            s_spk[warp] = spk;
        }
        __syncthreads();

        if (tid == 0) {
            float p = 0.0f;
            #pragma unroll
            for (int w = 0; w < ROWS_PER_BLOCK; w++) p += s_spk[w];
            g_partial[group] = p;
        }
        if (g + 1 < ROW_GROUPS) __syncthreads();
    }

    // ---- Grid-wide spin barrier (monotonic counter, replay-safe) ----
    if (tid == 0) {
        __threadfence();   // partials + row results visible before arrival
        const unsigned old = atomicAdd(&g_done, 1u);
        const unsigned target = (old & ~(unsigned)(MV_BLOCKS - 1)) + MV_BLOCKS;
        volatile unsigned* vd = &g_done;
        while ((int)(*vd - target) < 0) { }
        __threadfence();   // order spin-read before epilogue loads
    }
    __syncthreads();

    // ---- Distributed epilogue ----
    // Inhibition: every block redundantly sums the 1024 L2-hot partials
    // (exact integer sums). 256 threads x 1 float4 each.
    {
        const float4 p = __ldcg(reinterpret_cast<const float4*>(g_partial) + tid);
        float local = (p.x + p.y) + (p.z + p.w);
        #pragma unroll
        for (int o = 16; o > 0; o >>= 1) {
            local += __shfl_xor_sync(0xFFFFFFFFu, local, o);
        }
        if (lane == 0) s_red[warp] = local;
    }
    __syncthreads();

    float total = s_red[0];
    #pragma unroll
    for (int w = 1; w < THREADS / 32; w++) total += s_red[w];
    const float inhibition = total * 0.5f;

    // This block's 16 rows: one row per thread (tid < 16). Cross-block data
    // read with __ldcg (L2) to avoid any stale-L1 hazard.
    if (tid < EPI_ROWS) {
        const int r = blockIdx.x * EPI_ROWS + tid;
        const float s   = __ldcg(out + r);
        const float cur = __ldcg(g_current + r);
        const float vm  = v_mem[r];
        const float vt0 = v_th[r];

        const float v_new = (vm - inhibition + cur) * (1.0f - s) * 0.5f;

        float vt = vt0 + (s - 0.1f) * 0.01f;
        vt = fminf(fmaxf(vt, 0.2f), 5.0f);

        out[OUT_F + r]     = v_new;
        out[2 * OUT_F + r] = vt;
    }
}

extern "C" void kernel_launch(void* const* d_in, const int* in_sizes, int n_in,
                              void* d_out, int out_size)
{
    const float* spike_input = (const float*)d_in[0];   // [1, 8192]
    const float* syn         = (const float*)d_in[1];   // [8192, 8192]
    const float* v_mem       = (const float*)d_in[2];   // [8192]
    const float* v_th        = (const float*)d_in[3];   // [8192]
    const float* noise       = (const float*)d_in[4];   // [8192]
    float* out = (float*)d_out;                          // 3 * 8192 floats

    snn_fused_kernel<<<MV_BLOCKS, THREADS>>>(
        spike_input, syn, v_mem, v_th, noise, out);
}